// round 5
// baseline (speedup 1.0000x reference)
#include <cuda_runtime.h>
#include <cuda_fp16.h>
#include <cstdint>

// Problem constants
#define BB   32
#define TT   2048
#define FF   512
#define UU   128
#define MM   (BB * TT)          // 65536 frames
#define NEG_BIG -1.0e9f

// score kernel tiling
#define MBLK 128                // frames per block
#define KC   32                 // K elements per chunk
#define NC   (FF / KC)          // 16 chunks
#define NTH  256                // 8 warps: 4 m-warps x 2 n-warps
#define NBLK (MM / MBLK)        // 512 blocks

// smem layout (dynamic)
#define ROWB  80                // 64B row + 16B pad -> conflict-free ldmatrix
#define ATILE (128 * ROWB)      // 10240 B
#define SM_A(b,h) (((b)*2+(h)) * ATILE)            //   0 .. 40960
#define SM_B(b,h) (40960 + ((b)*2+(h)) * ATILE)    // 40960 .. 81920
#define SM_FLAGS  81920                            // 128 int
#define SM_PART   82432                            // 128 x 2 float
#define SM_W2     83456                            // 128 float
#define SM_B1     83968                            // 128 float
#define SM_TOTAL  84480

// Static scratch
__device__ float   g_scores[MM];
__device__ int     g_topidx[MM];
__device__ __half  g_Whi[UU * FF];   // [u][k] fp16 hi
__device__ __half  g_Wlo[UU * FF];   // [u][k] fp16 residual

// ---------------- PTX helpers (baseline sm_80 features only) ----------------
__device__ __forceinline__ uint32_t smem_u32(const void* p) {
    uint32_t a;
    asm("{ .reg .u64 t; cvta.to.shared.u64 t, %1; cvt.u32.u64 %0, t; }" : "=r"(a) : "l"(p));
    return a;
}
__device__ __forceinline__ void ldm_x4(uint32_t* r, uint32_t addr) {
    asm volatile("ldmatrix.sync.aligned.m8n8.x4.shared.b16 {%0,%1,%2,%3}, [%4];"
                 : "=r"(r[0]), "=r"(r[1]), "=r"(r[2]), "=r"(r[3]) : "r"(addr));
}
__device__ __forceinline__ void mma16816(float* c, const uint32_t* a, const uint32_t* b) {
    asm volatile(
        "mma.sync.aligned.m16n8k16.row.col.f32.f16.f16.f32 "
        "{%0,%1,%2,%3}, {%4,%5,%6,%7}, {%8,%9}, {%0,%1,%2,%3};"
        : "+f"(c[0]), "+f"(c[1]), "+f"(c[2]), "+f"(c[3])
        : "r"(a[0]), "r"(a[1]), "r"(a[2]), "r"(a[3]), "r"(b[0]), "r"(b[1]));
}
__device__ __forceinline__ void cp16(uint32_t dst, const void* src) {
    asm volatile("cp.async.ca.shared.global [%0], [%1], 16;" :: "r"(dst), "l"(src) : "memory");
}
__device__ __forceinline__ void cp_commit() { asm volatile("cp.async.commit_group;" ::: "memory"); }
__device__ __forceinline__ void cp_wait0()  { asm volatile("cp.async.wait_group 0;"  ::: "memory"); }

// fp32 float4 -> fp16 hi/lo pair, packed cvt, 8B stores
__device__ __forceinline__ void cvt_store(float4 v, char* hip, char* lop) {
    __half2 h01 = __floats2half2_rn(v.x, v.y);
    __half2 h23 = __floats2half2_rn(v.z, v.w);
    float2  f01 = __half22float2(h01);
    float2  f23 = __half22float2(h23);
    __half2 l01 = __floats2half2_rn(v.x - f01.x, v.y - f01.y);
    __half2 l23 = __floats2half2_rn(v.z - f23.x, v.w - f23.y);
    uint2 H; H.x = *(uint32_t*)&h01; H.y = *(uint32_t*)&h23;
    uint2 L; L.x = *(uint32_t*)&l01; L.y = *(uint32_t*)&l23;
    *(uint2*)hip = H;
    *(uint2*)lop = L;
}

// ---------------------------------------------------------------------------
// Prep: split + transpose W1 [k=512][u=128] fp32 -> g_Whi/g_Wlo [u][k] fp16
// ---------------------------------------------------------------------------
__global__ void wsplit_kernel(const float* __restrict__ W1)
{
    int i = blockIdx.x * 256 + threadIdx.x;   // 0..65535
    int u = i >> 9, k = i & 511;
    float v = W1[(size_t)k * UU + u];
    __half h = __float2half_rn(v);
    __half l = __float2half_rn(v - __half2float(h));
    g_Whi[(size_t)u * FF + k] = h;
    g_Wlo[(size_t)u * FF + k] = l;
}

// ---------------------------------------------------------------------------
// Kernel A: fp16 2-split (3-term) score GEMM on mma.sync tensor cores.
// Also streams the 128MB zero-fill of `out` (hidden behind compute).
// ---------------------------------------------------------------------------
__global__ __launch_bounds__(NTH)
void score_mma_kernel(const float* __restrict__ x,
                      const float* __restrict__ b1,
                      const float* __restrict__ W2,
                      const float* __restrict__ b2,
                      float4* __restrict__ out4)
{
    extern __shared__ char smem[];
    const uint32_t sb = smem_u32(smem);
    const int tid  = threadIdx.x;
    const int lane = tid & 31;
    const int wid  = tid >> 5;
    const int wm   = wid & 3;          // m-warp: frames wm*32..+31
    const int wn   = wid >> 2;         // n-warp: u wn*64..+63
    const int m0   = blockIdx.x * MBLK;

    int*   flags = (int*)(smem + SM_FLAGS);
    float* part  = (float*)(smem + SM_PART);
    float* w2s   = (float*)(smem + SM_W2);
    float* b1s   = (float*)(smem + SM_B1);

    if (tid < UU) { w2s[tid] = W2[tid]; b1s[tid] = b1[tid]; flags[tid] = 0; }

    // ldmatrix lane-offset precompute
    const int la = lane & 7, lb = (lane >> 3) & 1, lc = lane >> 4;
    const uint32_t a_lane = (uint32_t)(la + lb * 8) * ROWB + (uint32_t)lc * 16;
    const uint32_t b_lane = (uint32_t)(la + lc * 8) * ROWB + (uint32_t)lb * 16;

    const float* xa = x + (size_t)m0 * FF;

    // per-thread validity predicates for the 4 fixed rows this thread loads
    bool pr[4] = {false, false, false, false};

    // ---- prologue: fill chunk 0 into buffer 0 ----
#pragma unroll
    for (int i = 0; i < 4; i++) {
        int idx = tid + i * NTH;          // 0..1023
        int row = idx >> 3, c = idx & 7;
        float4 v = *(const float4*)(xa + (size_t)row * FF + c * 4);
        pr[i] = pr[i] || (v.x != 0.f || v.y != 0.f || v.z != 0.f || v.w != 0.f);
        cvt_store(v, smem + SM_A(0,0) + row * ROWB + c * 8,
                     smem + SM_A(0,1) + row * ROWB + c * 8);
    }
#pragma unroll
    for (int i = 0; i < 2; i++) {
        int idx = tid + i * NTH;          // 0..511
        int row = idx >> 2, c = idx & 3;
        cp16(sb + SM_B(0,0) + row * ROWB + c * 16, (const void*)(g_Whi + (size_t)row * FF + c * 8));
        cp16(sb + SM_B(0,1) + row * ROWB + c * 16, (const void*)(g_Wlo + (size_t)row * FF + c * 8));
    }
    cp_commit(); cp_wait0();
    __syncthreads();

    float acc[2][8][4];
#pragma unroll
    for (int mt = 0; mt < 2; mt++)
#pragma unroll
        for (int nt = 0; nt < 8; nt++)
#pragma unroll
            for (int c = 0; c < 4; c++) acc[mt][nt][c] = 0.0f;

    const float4 zero4 = make_float4(0.f, 0.f, 0.f, 0.f);
    const long long zbase = (long long)blockIdx.x * 16384;

    for (int t = 0; t < NC; t++) {
        const int cb = t & 1, nb = cb ^ 1;
        const bool has_next = (t + 1 < NC);

        // prefetch half0 of next A chunk (rows 0..63) + B via cp.async
        float4 rxa[2];
        if (has_next) {
#pragma unroll
            for (int i = 0; i < 2; i++) {
                int idx = tid + i * NTH;
                int row = idx >> 3, c = idx & 7;
                rxa[i] = *(const float4*)(xa + (size_t)row * FF + (t + 1) * KC + c * 4);
            }
#pragma unroll
            for (int i = 0; i < 2; i++) {
                int idx = tid + i * NTH;
                int row = idx >> 2, c = idx & 3;
                cp16(sb + SM_B(nb,0) + row * ROWB + c * 16,
                     (const void*)(g_Whi + (size_t)row * FF + (t + 1) * KC + c * 8));
                cp16(sb + SM_B(nb,1) + row * ROWB + c * 16,
                     (const void*)(g_Wlo + (size_t)row * FF + (t + 1) * KC + c * 8));
            }
            cp_commit();
        }

        // ---- compute ks = 0 ----
        {
            uint32_t Ah[2][4], Al[2][4];
            ldm_x4(Ah[0], sb + SM_A(cb,0) + (uint32_t)(wm*32 +  0) * ROWB + a_lane);
            ldm_x4(Ah[1], sb + SM_A(cb,0) + (uint32_t)(wm*32 + 16) * ROWB + a_lane);
            ldm_x4(Al[0], sb + SM_A(cb,1) + (uint32_t)(wm*32 +  0) * ROWB + a_lane);
            ldm_x4(Al[1], sb + SM_A(cb,1) + (uint32_t)(wm*32 + 16) * ROWB + a_lane);
#pragma unroll
            for (int p = 0; p < 4; p++) {
                uint32_t Bh[4], Bl[4];
                ldm_x4(Bh, sb + SM_B(cb,0) + (uint32_t)(wn*64 + p*16) * ROWB + b_lane);
                ldm_x4(Bl, sb + SM_B(cb,1) + (uint32_t)(wn*64 + p*16) * ROWB + b_lane);
#pragma unroll
                for (int mt = 0; mt < 2; mt++) {
                    mma16816(acc[mt][2*p  ], Ah[mt], Bh + 0);
                    mma16816(acc[mt][2*p+1], Ah[mt], Bh + 2);
                    mma16816(acc[mt][2*p  ], Ah[mt], Bl + 0);
                    mma16816(acc[mt][2*p+1], Ah[mt], Bl + 2);
                    mma16816(acc[mt][2*p  ], Al[mt], Bh + 0);
                    mma16816(acc[mt][2*p+1], Al[mt], Bh + 2);
                }
            }
        }

        // store half0, prefetch half1 (rows 64..127)
        float4 rxb[2];
        if (has_next) {
#pragma unroll
            for (int i = 0; i < 2; i++) {
                int idx = tid + i * NTH;
                int row = idx >> 3, c = idx & 7;
                pr[i] = pr[i] || (rxa[i].x != 0.f || rxa[i].y != 0.f ||
                                  rxa[i].z != 0.f || rxa[i].w != 0.f);
                cvt_store(rxa[i], smem + SM_A(nb,0) + row * ROWB + c * 8,
                                  smem + SM_A(nb,1) + row * ROWB + c * 8);
            }
#pragma unroll
            for (int i = 2; i < 4; i++) {
                int idx = tid + i * NTH;
                int row = idx >> 3, c = idx & 7;
                rxb[i-2] = *(const float4*)(xa + (size_t)row * FF + (t + 1) * KC + c * 4);
            }
        }

        // ---- compute ks = 1 ----
        {
            uint32_t Ah[2][4], Al[2][4];
            ldm_x4(Ah[0], sb + SM_A(cb,0) + (uint32_t)(wm*32 +  0) * ROWB + a_lane + 32);
            ldm_x4(Ah[1], sb + SM_A(cb,0) + (uint32_t)(wm*32 + 16) * ROWB + a_lane + 32);
            ldm_x4(Al[0], sb + SM_A(cb,1) + (uint32_t)(wm*32 +  0) * ROWB + a_lane + 32);
            ldm_x4(Al[1], sb + SM_A(cb,1) + (uint32_t)(wm*32 + 16) * ROWB + a_lane + 32);
#pragma unroll
            for (int p = 0; p < 4; p++) {
                uint32_t Bh[4], Bl[4];
                ldm_x4(Bh, sb + SM_B(cb,0) + (uint32_t)(wn*64 + p*16) * ROWB + b_lane + 32);
                ldm_x4(Bl, sb + SM_B(cb,1) + (uint32_t)(wn*64 + p*16) * ROWB + b_lane + 32);
#pragma unroll
                for (int mt = 0; mt < 2; mt++) {
                    mma16816(acc[mt][2*p  ], Ah[mt], Bh + 0);
                    mma16816(acc[mt][2*p+1], Ah[mt], Bh + 2);
                    mma16816(acc[mt][2*p  ], Ah[mt], Bl + 0);
                    mma16816(acc[mt][2*p+1], Ah[mt], Bl + 2);
                    mma16816(acc[mt][2*p  ], Al[mt], Bh + 0);
                    mma16816(acc[mt][2*p+1], Al[mt], Bh + 2);
                }
            }
        }

        // store half1
        if (has_next) {
#pragma unroll
            for (int i = 2; i < 4; i++) {
                int idx = tid + i * NTH;
                int row = idx >> 3, c = idx & 7;
                float4 v = rxb[i-2];
                pr[i] = pr[i] || (v.x != 0.f || v.y != 0.f || v.z != 0.f || v.w != 0.f);
                cvt_store(v, smem + SM_A(nb,0) + row * ROWB + c * 8,
                             smem + SM_A(nb,1) + row * ROWB + c * 8);
            }
        }

        // stream 4 zero float4s of the output (64 per thread over 16 chunks)
#pragma unroll
        for (int j = 0; j < 4; j++)
            __stcs(&out4[zbase + (long long)t * 1024 + j * 256 + tid], zero4);

        if (has_next) cp_wait0();
        __syncthreads();
    }

    // ---- write validity flags (benign 1-races), then epilogue ----
#pragma unroll
    for (int i = 0; i < 4; i++)
        if (pr[i]) flags[(tid + i * NTH) >> 3] = 1;

    const float b2v = b2[0];
#pragma unroll
    for (int mt = 0; mt < 2; mt++) {
        float p0 = 0.f, p1 = 0.f;
#pragma unroll
        for (int nt = 0; nt < 8; nt++) {
            int u0 = wn * 64 + nt * 8 + (lane & 3) * 2;
            float w0 = w2s[u0], w1 = w2s[u0+1], c0 = b1s[u0], c1 = b1s[u0+1];
            p0 += fmaxf(acc[mt][nt][0] + c0, 0.f) * w0 + fmaxf(acc[mt][nt][1] + c1, 0.f) * w1;
            p1 += fmaxf(acc[mt][nt][2] + c0, 0.f) * w0 + fmaxf(acc[mt][nt][3] + c1, 0.f) * w1;
        }
        p0 += __shfl_xor_sync(0xffffffffu, p0, 1);
        p0 += __shfl_xor_sync(0xffffffffu, p0, 2);
        p1 += __shfl_xor_sync(0xffffffffu, p1, 1);
        p1 += __shfl_xor_sync(0xffffffffu, p1, 2);
        if ((lane & 3) == 0) {
            int r = lane >> 2;
            part[(wm*32 + mt*16 +     r) * 2 + wn] = p0;
            part[(wm*32 + mt*16 + 8 + r) * 2 + wn] = p1;
        }
    }
    __syncthreads();
    if (tid < MBLK) {
        float s = part[tid * 2] + part[tid * 2 + 1] + b2v;
        g_scores[m0 + tid] = flags[tid] ? s : NEG_BIG;
    }
}

// ---------------------------------------------------------------------------
// Kernel B: per-batch-row exact top-k via full bitonic sort of 2048 keys.
// Emits a compact top-index list.
// ---------------------------------------------------------------------------
__global__ __launch_bounds__(512)
void topk_kernel(const int* __restrict__ kptr)
{
    __shared__ unsigned long long keys[TT];
    const int b   = blockIdx.x;
    const int tid = threadIdx.x;

    for (int t = tid; t < TT; t += 512) {
        float s = g_scores[b * TT + t];
        unsigned u = __float_as_uint(s);
        u = (u & 0x80000000u) ? ~u : (u | 0x80000000u);
        keys[t] = ((unsigned long long)u << 32) | (unsigned)(~t);
    }
    __syncthreads();

    for (int kk = 2; kk <= TT; kk <<= 1) {
        for (int j = kk >> 1; j > 0; j >>= 1) {
            for (int i = tid; i < TT; i += 512) {
                int ixj = i ^ j;
                if (ixj > i) {
                    unsigned long long a = keys[i], c = keys[ixj];
                    bool desc = ((i & kk) == 0);
                    bool sw = desc ? (a < c) : (a > c);
                    if (sw) { keys[i] = c; keys[ixj] = a; }
                }
            }
            __syncthreads();
        }
    }

    const int k = *kptr;
    for (int t = tid; t < k && t < TT; t += 512) {
        int frame = (int)(~(unsigned)(keys[t] & 0xffffffffu)) & (TT - 1);
        g_topidx[b * TT + t] = frame;
    }
}

// ---------------------------------------------------------------------------
// Kernel C: scatter-copy only the selected frames (~4MB instead of 128MB).
// Grid (BB, 16), 128 threads. Zeros were written by score_mma_kernel.
// ---------------------------------------------------------------------------
__global__ __launch_bounds__(128)
void scatter_kernel(const float* __restrict__ x, float* __restrict__ out,
                    const int* __restrict__ kptr)
{
    const int b    = blockIdx.x;
    const int part = blockIdx.y;
    const int tid  = threadIdx.x;
    const int k    = *kptr;

    for (int r = part; r < k && r < TT; r += 16) {
        int frame = g_topidx[b * TT + r];
        const float4* src = (const float4*)(x   + ((size_t)b * TT + frame) * FF);
        float4*       dst = (float4*)      (out + ((size_t)b * TT + frame) * FF);
        if (tid < 128) dst[tid] = src[tid];   // FF/4 = 128 float4 per frame
    }
}

// ---------------------------------------------------------------------------
extern "C" void kernel_launch(void* const* d_in, const int* in_sizes, int n_in,
                              void* d_out, int out_size)
{
    const float* x  = (const float*)d_in[0];
    const float* W1 = (const float*)d_in[1];
    const float* b1 = (const float*)d_in[2];
    const float* W2 = (const float*)d_in[3];
    const float* b2 = (const float*)d_in[4];
    const int*   kp = (const int*)d_in[5];
    float* out = (float*)d_out;

    cudaFuncSetAttribute(score_mma_kernel,
                         cudaFuncAttributeMaxDynamicSharedMemorySize, SM_TOTAL);

    wsplit_kernel<<<UU * FF / 256, 256>>>(W1);
    score_mma_kernel<<<NBLK, NTH, SM_TOTAL>>>(x, b1, W2, b2, (float4*)out);
    topk_kernel<<<BB, 512>>>(kp);
    scatter_kernel<<<dim3(BB, 16), 128>>>(x, out, kp);
}

// round 7
// speedup vs baseline: 1.2109x; 1.2109x over previous
#include <cuda_runtime.h>
#include <cuda_fp16.h>
#include <cstdint>

// Problem constants
#define BB   32
#define TT   2048
#define FF   512
#define UU   128
#define MM   (BB * TT)          // 65536 frames
#define NEG_BIG -1.0e9f

// score kernel tiling
#define MBLK 128                // frames per block
#define KC   32                 // K elements per chunk
#define NC   (FF / KC)          // 16 chunks
#define NTH  512                // 16 warps: 4 m-warps x 4 n-warps
#define NBLK (MM / MBLK)        // 512 blocks

// smem layout (dynamic)
#define ROWB  80                // 64B row + 16B pad -> conflict-free ldmatrix
#define ATILE (128 * ROWB)      // 10240 B
#define SM_A(b,h) (((b)*2+(h)) * ATILE)            //   0 .. 40960
#define SM_B(b,h) (40960 + ((b)*2+(h)) * ATILE)    // 40960 .. 81920
#define SM_FLAGS  81920                            // 128 int
#define SM_PART   82432                            // 128 x 4 float
#define SM_W2     84480                            // 128 float
#define SM_B1     84992                            // 128 float
#define SM_TOTAL  85504

// Static scratch
__device__ float          g_scores[MM];
__device__ unsigned char  g_sel[MM];
__device__ __half         g_Whi[UU * FF];   // [u][k] fp16 hi
__device__ __half         g_Wlo[UU * FF];   // [u][k] fp16 residual

// ---------------- PTX helpers (baseline sm_80 features only) ----------------
__device__ __forceinline__ uint32_t smem_u32(const void* p) {
    uint32_t a;
    asm("{ .reg .u64 t; cvta.to.shared.u64 t, %1; cvt.u32.u64 %0, t; }" : "=r"(a) : "l"(p));
    return a;
}
__device__ __forceinline__ void ldm_x4(uint32_t* r, uint32_t addr) {
    asm volatile("ldmatrix.sync.aligned.m8n8.x4.shared.b16 {%0,%1,%2,%3}, [%4];"
                 : "=r"(r[0]), "=r"(r[1]), "=r"(r[2]), "=r"(r[3]) : "r"(addr));
}
__device__ __forceinline__ void mma16816(float* c, const uint32_t* a, const uint32_t* b) {
    asm volatile(
        "mma.sync.aligned.m16n8k16.row.col.f32.f16.f16.f32 "
        "{%0,%1,%2,%3}, {%4,%5,%6,%7}, {%8,%9}, {%0,%1,%2,%3};"
        : "+f"(c[0]), "+f"(c[1]), "+f"(c[2]), "+f"(c[3])
        : "r"(a[0]), "r"(a[1]), "r"(a[2]), "r"(a[3]), "r"(b[0]), "r"(b[1]));
}
__device__ __forceinline__ void cp16(uint32_t dst, const void* src) {
    asm volatile("cp.async.ca.shared.global [%0], [%1], 16;" :: "r"(dst), "l"(src) : "memory");
}
__device__ __forceinline__ void cp_commit() { asm volatile("cp.async.commit_group;" ::: "memory"); }
__device__ __forceinline__ void cp_wait0()  { asm volatile("cp.async.wait_group 0;"  ::: "memory"); }

// fp32 float4 -> fp16 hi/lo pair, packed cvt, 8B stores
__device__ __forceinline__ void cvt_store(float4 v, char* hip, char* lop) {
    __half2 h01 = __floats2half2_rn(v.x, v.y);
    __half2 h23 = __floats2half2_rn(v.z, v.w);
    float2  f01 = __half22float2(h01);
    float2  f23 = __half22float2(h23);
    __half2 l01 = __floats2half2_rn(v.x - f01.x, v.y - f01.y);
    __half2 l23 = __floats2half2_rn(v.z - f23.x, v.w - f23.y);
    uint2 H; H.x = *(uint32_t*)&h01; H.y = *(uint32_t*)&h23;
    uint2 L; L.x = *(uint32_t*)&l01; L.y = *(uint32_t*)&l23;
    *(uint2*)hip = H;
    *(uint2*)lop = L;
}

// ---------------------------------------------------------------------------
// Prep: split + transpose W1 [k=512][u=128] fp32 -> g_Whi/g_Wlo [u][k] fp16
// ---------------------------------------------------------------------------
__global__ void wsplit_kernel(const float* __restrict__ W1)
{
    int i = blockIdx.x * 256 + threadIdx.x;   // 0..65535
    int u = i >> 9, k = i & 511;
    float v = W1[(size_t)k * UU + u];
    __half h = __float2half_rn(v);
    __half l = __float2half_rn(v - __half2float(h));
    g_Whi[(size_t)u * FF + k] = h;
    g_Wlo[(size_t)u * FF + k] = l;
}

// ---------------------------------------------------------------------------
// Kernel A: fp16 2-split (3-term) score GEMM on mma.sync tensor cores.
// 16 warps: warp (wm,wn) computes M=32 x N=32 (2x4 mma tiles x 3 splits).
// ---------------------------------------------------------------------------
__global__ __launch_bounds__(NTH)
void score_mma_kernel(const float* __restrict__ x,
                      const float* __restrict__ b1,
                      const float* __restrict__ W2,
                      const float* __restrict__ b2)
{
    extern __shared__ char smem[];
    const uint32_t sb = smem_u32(smem);
    const int tid  = threadIdx.x;
    const int lane = tid & 31;
    const int wid  = tid >> 5;
    const int wm   = wid & 3;          // m-warp: frames wm*32..+31
    const int wn   = wid >> 2;         // n-warp: u wn*32..+31
    const int m0   = blockIdx.x * MBLK;

    int*   flags = (int*)(smem + SM_FLAGS);
    float* part  = (float*)(smem + SM_PART);
    float* w2s   = (float*)(smem + SM_W2);
    float* b1s   = (float*)(smem + SM_B1);

    if (tid < UU) { w2s[tid] = W2[tid]; b1s[tid] = b1[tid]; flags[tid] = 0; }

    // ldmatrix lane-offset precompute
    const int la = lane & 7, lb = (lane >> 3) & 1, lc = lane >> 4;
    const uint32_t a_lane = (uint32_t)(la + lb * 8) * ROWB + (uint32_t)lc * 16;
    const uint32_t b_lane = (uint32_t)(la + lc * 8) * ROWB + (uint32_t)lb * 16;

    const float* xa = x + (size_t)m0 * FF;

    // per-thread validity predicates for the 2 fixed rows this thread loads
    bool pr[2] = {false, false};

    // ---- prologue: fill chunk 0 into buffer 0 ----
#pragma unroll
    for (int i = 0; i < 2; i++) {
        int idx = tid + i * NTH;          // 0..1023
        int row = idx >> 3, c = idx & 7;
        float4 v = *(const float4*)(xa + (size_t)row * FF + c * 4);
        pr[i] = pr[i] || (v.x != 0.f || v.y != 0.f || v.z != 0.f || v.w != 0.f);
        cvt_store(v, smem + SM_A(0,0) + row * ROWB + c * 8,
                     smem + SM_A(0,1) + row * ROWB + c * 8);
    }
    {
        int row = tid >> 2, c = tid & 3;  // 512 threads cover 128 rows x 4
        cp16(sb + SM_B(0,0) + row * ROWB + c * 16, (const void*)(g_Whi + (size_t)row * FF + c * 8));
        cp16(sb + SM_B(0,1) + row * ROWB + c * 16, (const void*)(g_Wlo + (size_t)row * FF + c * 8));
    }
    cp_commit(); cp_wait0();
    __syncthreads();

    float acc[2][4][4];
#pragma unroll
    for (int mt = 0; mt < 2; mt++)
#pragma unroll
        for (int nt = 0; nt < 4; nt++)
#pragma unroll
            for (int c = 0; c < 4; c++) acc[mt][nt][c] = 0.0f;

    for (int t = 0; t < NC; t++) {
        const int cb = t & 1, nb = cb ^ 1;
        const bool has_next = (t + 1 < NC);

        // prefetch next chunk: A into regs, B via cp.async
        float4 rx[2];
        if (has_next) {
#pragma unroll
            for (int i = 0; i < 2; i++) {
                int idx = tid + i * NTH;
                int row = idx >> 3, c = idx & 7;
                rx[i] = *(const float4*)(xa + (size_t)row * FF + (t + 1) * KC + c * 4);
            }
            {
                int row = tid >> 2, c = tid & 3;
                cp16(sb + SM_B(nb,0) + row * ROWB + c * 16,
                     (const void*)(g_Whi + (size_t)row * FF + (t + 1) * KC + c * 8));
                cp16(sb + SM_B(nb,1) + row * ROWB + c * 16,
                     (const void*)(g_Wlo + (size_t)row * FF + (t + 1) * KC + c * 8));
            }
            cp_commit();
        }

        // compute on current buffer: 2 K16 steps x (2m x 4n x 3 splits) mma
#pragma unroll
        for (int ks = 0; ks < 2; ks++) {
            const uint32_t kb = (uint32_t)ks * 32;
            uint32_t Ah[2][4], Al[2][4];
            ldm_x4(Ah[0], sb + SM_A(cb,0) + (uint32_t)(wm*32 +  0) * ROWB + a_lane + kb);
            ldm_x4(Ah[1], sb + SM_A(cb,0) + (uint32_t)(wm*32 + 16) * ROWB + a_lane + kb);
            ldm_x4(Al[0], sb + SM_A(cb,1) + (uint32_t)(wm*32 +  0) * ROWB + a_lane + kb);
            ldm_x4(Al[1], sb + SM_A(cb,1) + (uint32_t)(wm*32 + 16) * ROWB + a_lane + kb);
#pragma unroll
            for (int p = 0; p < 2; p++) {
                uint32_t Bh[4], Bl[4];
                ldm_x4(Bh, sb + SM_B(cb,0) + (uint32_t)(wn*32 + p*16) * ROWB + b_lane + kb);
                ldm_x4(Bl, sb + SM_B(cb,1) + (uint32_t)(wn*32 + p*16) * ROWB + b_lane + kb);
#pragma unroll
                for (int mt = 0; mt < 2; mt++) {
                    mma16816(acc[mt][2*p  ], Ah[mt], Bh + 0);
                    mma16816(acc[mt][2*p+1], Ah[mt], Bh + 2);
                    mma16816(acc[mt][2*p  ], Ah[mt], Bl + 0);
                    mma16816(acc[mt][2*p+1], Ah[mt], Bl + 2);
                    mma16816(acc[mt][2*p  ], Al[mt], Bh + 0);
                    mma16816(acc[mt][2*p+1], Al[mt], Bh + 2);
                }
            }
        }

        // store prefetched A into next buffer, drain B cp.async
        if (has_next) {
#pragma unroll
            for (int i = 0; i < 2; i++) {
                int idx = tid + i * NTH;
                int row = idx >> 3, c = idx & 7;
                float4 v = rx[i];
                pr[i] = pr[i] || (v.x != 0.f || v.y != 0.f || v.z != 0.f || v.w != 0.f);
                cvt_store(v, smem + SM_A(nb,0) + row * ROWB + c * 8,
                             smem + SM_A(nb,1) + row * ROWB + c * 8);
            }
            cp_wait0();
        }
        __syncthreads();
    }

    // ---- write validity flags (benign 1-races), then epilogue ----
#pragma unroll
    for (int i = 0; i < 2; i++)
        if (pr[i]) flags[(tid + i * NTH) >> 3] = 1;

    const float b2v = b2[0];
#pragma unroll
    for (int mt = 0; mt < 2; mt++) {
        float p0 = 0.f, p1 = 0.f;
#pragma unroll
        for (int nt = 0; nt < 4; nt++) {
            int u0 = wn * 32 + nt * 8 + (lane & 3) * 2;
            float w0 = w2s[u0], w1 = w2s[u0+1], c0 = b1s[u0], c1 = b1s[u0+1];
            p0 += fmaxf(acc[mt][nt][0] + c0, 0.f) * w0 + fmaxf(acc[mt][nt][1] + c1, 0.f) * w1;
            p1 += fmaxf(acc[mt][nt][2] + c0, 0.f) * w0 + fmaxf(acc[mt][nt][3] + c1, 0.f) * w1;
        }
        p0 += __shfl_xor_sync(0xffffffffu, p0, 1);
        p0 += __shfl_xor_sync(0xffffffffu, p0, 2);
        p1 += __shfl_xor_sync(0xffffffffu, p1, 1);
        p1 += __shfl_xor_sync(0xffffffffu, p1, 2);
        if ((lane & 3) == 0) {
            int r = lane >> 2;
            part[(wm*32 + mt*16 +     r) * 4 + wn] = p0;
            part[(wm*32 + mt*16 + 8 + r) * 4 + wn] = p1;
        }
    }
    __syncthreads();
    if (tid < MBLK) {
        float s = part[tid*4] + part[tid*4+1] + part[tid*4+2] + part[tid*4+3] + b2v;
        g_scores[m0 + tid] = flags[tid] ? s : NEG_BIG;
    }
}

// ---------------------------------------------------------------------------
// Kernel B: per-batch-row exact top-k via full bitonic sort of 2048 keys.
// ---------------------------------------------------------------------------
__global__ __launch_bounds__(512)
void topk_kernel(const int* __restrict__ kptr)
{
    __shared__ unsigned long long keys[TT];
    const int b   = blockIdx.x;
    const int tid = threadIdx.x;

    for (int t = tid; t < TT; t += 512) {
        float s = g_scores[b * TT + t];
        unsigned u = __float_as_uint(s);
        u = (u & 0x80000000u) ? ~u : (u | 0x80000000u);
        keys[t] = ((unsigned long long)u << 32) | (unsigned)(~t);
    }
    __syncthreads();

    for (int kk = 2; kk <= TT; kk <<= 1) {
        for (int j = kk >> 1; j > 0; j >>= 1) {
            for (int i = tid; i < TT; i += 512) {
                int ixj = i ^ j;
                if (ixj > i) {
                    unsigned long long a = keys[i], c = keys[ixj];
                    bool desc = ((i & kk) == 0);
                    bool sw = desc ? (a < c) : (a > c);
                    if (sw) { keys[i] = c; keys[ixj] = a; }
                }
            }
            __syncthreads();
        }
    }

    const int k = *kptr;
    for (int t = tid; t < TT; t += 512) {
        int frame = (int)(~(unsigned)(keys[t] & 0xffffffffu)) & (TT - 1);
        g_sel[b * TT + frame] = (t < k) ? 1 : 0;
    }
}

// ---------------------------------------------------------------------------
// Kernel C: out = x * sel (write-only zeros for unselected frames).
// ---------------------------------------------------------------------------
__global__ __launch_bounds__(256)
void gather_kernel(const float* __restrict__ x, float* __restrict__ out)
{
    const long long idx = (long long)blockIdx.x * blockDim.x + threadIdx.x;
    const int frame = (int)(idx >> 7);
    float4 o = make_float4(0.f, 0.f, 0.f, 0.f);
    if (g_sel[frame])
        o = ((const float4*)x)[idx];
    ((float4*)out)[idx] = o;
}

// ---------------------------------------------------------------------------
extern "C" void kernel_launch(void* const* d_in, const int* in_sizes, int n_in,
                              void* d_out, int out_size)
{
    const float* x  = (const float*)d_in[0];
    const float* W1 = (const float*)d_in[1];
    const float* b1 = (const float*)d_in[2];
    const float* W2 = (const float*)d_in[3];
    const float* b2 = (const float*)d_in[4];
    const int*   kp = (const int*)d_in[5];
    float* out = (float*)d_out;

    cudaFuncSetAttribute(score_mma_kernel,
                         cudaFuncAttributeMaxDynamicSharedMemorySize, SM_TOTAL);

    wsplit_kernel<<<UU * FF / 256, 256>>>(W1);
    score_mma_kernel<<<NBLK, NTH, SM_TOTAL>>>(x, b1, W2, b2);
    topk_kernel<<<BB, 512>>>(kp);
    const long long nvec4 = (long long)MM * FF / 4;
    gather_kernel<<<(unsigned)(nvec4 / 256), 256>>>(x, out);
}